// round 3
// baseline (speedup 1.0000x reference)
#include <cuda_runtime.h>
#include <math.h>

#define NTOK  8192
#define DIM   768
#define NH    12
#define HD    64
#define FF    3072
#define NE    4
#define SEQ   2048
#define BATCH 4

// ---------------- scratch (static device globals; no allocation) ----------------
__device__ float g_x2[NTOK * DIM];      // LN output (reused for LN1 and LN2)
__device__ float g_t1[NTOK * FF];       // GEMM scratch (W1 result / attn output / MoE h)
__device__ float g_q[NTOK * DIM];
__device__ float g_k[NTOK * DIM];
__device__ float g_v[NTOK * DIM];
__device__ float g_kv[BATCH * NH * HD * HD];
__device__ float g_ksum[BATCH * NH * HD];
__device__ float g_comb[NTOK * NE];
__device__ int   g_cnt[NE];
__device__ int   g_idx[NE * NTOK];

__device__ __forceinline__ float phi_f(float x)  { return x > 0.f ? x + 1.f : expf(x); }    // elu(x)+1
__device__ __forceinline__ float silu_f(float x) { return x / (1.f + expf(-x)); }

// ---------------- LayerNorm: one block per row ----------------
__global__ void ln_kernel(const float* __restrict__ X, const float* __restrict__ g,
                          const float* __restrict__ be, float* __restrict__ out) {
    int row = blockIdx.x;
    int tid = threadIdx.x;                  // 256 threads, 3 elems each (768)
    __shared__ float red[256];
    __shared__ float s_m, s_r;
    const float* xr = X + (size_t)row * DIM;
    float v0 = xr[tid], v1 = xr[tid + 256], v2 = xr[tid + 512];
    red[tid] = v0 + v1 + v2;
    __syncthreads();
    for (int o = 128; o > 0; o >>= 1) { if (tid < o) red[tid] += red[tid + o]; __syncthreads(); }
    if (tid == 0) s_m = red[0] * (1.f / DIM);
    __syncthreads();
    float m = s_m;
    float d0 = v0 - m, d1 = v1 - m, d2 = v2 - m;
    red[tid] = d0 * d0 + d1 * d1 + d2 * d2;
    __syncthreads();
    for (int o = 128; o > 0; o >>= 1) { if (tid < o) red[tid] += red[tid + o]; __syncthreads(); }
    if (tid == 0) s_r = rsqrtf(red[0] * (1.f / DIM) + 1e-5f);
    __syncthreads();
    float r = s_r;
    float* orow = out + (size_t)row * DIM;
    orow[tid]       = d0 * r * g[tid]       + be[tid];
    orow[tid + 256] = d1 * r * g[tid + 256] + be[tid + 256];
    orow[tid + 512] = d2 * r * g[tid + 512] + be[tid + 512];
}

// ---------------- SGEMM 128x128x8, double buffered, 8x8 per thread ----------------
// A[M,K] row-major, W[K,N] row-major, C row length = N.
// mode 0: C[r] = acc + bias                      (idx!=null remaps A rows; cnt overrides M)
// mode 1: C[r] = acc + bias + R[r]               (residual add)
// mode 2: C[idx[r]] += comb[idx[r]*NE+e] * (acc + bias)   (scatter-accumulate)
// mode 3: C[r] = silu(R[r]) * (acc + bias)       (fused GLU epilogue; idx remaps A rows)
__global__ __launch_bounds__(256) void sgemm_kernel(
    const float* __restrict__ A, const float* __restrict__ W,
    const float* __restrict__ bias, float* __restrict__ C,
    int M, int N, int K,
    const int* __restrict__ idx, const int* __restrict__ cntPtr,
    int mode, const float* __restrict__ R,
    const float* __restrict__ comb, int expert)
{
    int Mcur = cntPtr ? *cntPtr : M;
    int mtile = blockIdx.y * 128;
    if (mtile >= Mcur) return;
    int ntile = blockIdx.x * 128;
    int tid = threadIdx.x;

    __shared__ float As[2][8][128];
    __shared__ float Bs[2][8][128];

    int am = tid >> 1;              // 0..127 : A row within tile
    int ak = (tid & 1) * 4;         // 0 or 4 : A k offset
    int grow = mtile + am;
    const float* Ap = nullptr;
    if (grow < Mcur) {
        int arow = (mode != 2 && idx) ? idx[grow] : grow;
        Ap = A + (size_t)arow * K + ak;
    }
    int bk = tid >> 5;              // 0..7
    int bn = (tid & 31) * 4;        // 0..124
    const float* Wp = W + (size_t)bk * N + ntile + bn;

    int tx = tid & 15;
    int ty = tid >> 4;

    float acc[8][8];
    #pragma unroll
    for (int i = 0; i < 8; i++)
        #pragma unroll
        for (int j = 0; j < 8; j++) acc[i][j] = 0.f;

    float4 ra = make_float4(0.f, 0.f, 0.f, 0.f), rb;
    if (Ap) ra = *(const float4*)Ap;
    rb = *(const float4*)Wp;
    As[0][ak + 0][am] = ra.x; As[0][ak + 1][am] = ra.y;
    As[0][ak + 2][am] = ra.z; As[0][ak + 3][am] = ra.w;
    *(float4*)(&Bs[0][bk][bn]) = rb;
    __syncthreads();

    int KT = K >> 3;
    int cur = 0;
    for (int kt = 0; kt < KT; kt++) {
        if (kt + 1 < KT) {
            int ko = (kt + 1) << 3;
            ra = Ap ? *(const float4*)(Ap + ko) : make_float4(0.f, 0.f, 0.f, 0.f);
            rb = *(const float4*)(Wp + (size_t)ko * N);
        }
        #pragma unroll
        for (int kk = 0; kk < 8; kk++) {
            float4 a0 = *(const float4*)(&As[cur][kk][ty * 4]);
            float4 a1 = *(const float4*)(&As[cur][kk][64 + ty * 4]);
            float4 b0 = *(const float4*)(&Bs[cur][kk][tx * 4]);
            float4 b1 = *(const float4*)(&Bs[cur][kk][64 + tx * 4]);
            float av[8] = {a0.x, a0.y, a0.z, a0.w, a1.x, a1.y, a1.z, a1.w};
            float bv[8] = {b0.x, b0.y, b0.z, b0.w, b1.x, b1.y, b1.z, b1.w};
            #pragma unroll
            for (int i = 0; i < 8; i++)
                #pragma unroll
                for (int j = 0; j < 8; j++)
                    acc[i][j] += av[i] * bv[j];
        }
        if (kt + 1 < KT) {
            int nb = cur ^ 1;
            As[nb][ak + 0][am] = ra.x; As[nb][ak + 1][am] = ra.y;
            As[nb][ak + 2][am] = ra.z; As[nb][ak + 3][am] = ra.w;
            *(float4*)(&Bs[nb][bk][bn]) = rb;
            __syncthreads();
            cur = nb;
        }
    }

    #pragma unroll
    for (int i = 0; i < 8; i++) {
        int r = mtile + ((i < 4) ? (ty * 4 + i) : (64 + ty * 4 + i - 4));
        if (r >= Mcur) continue;
        if (mode == 2) {
            int cr = idx[r];
            float wgt = comb[cr * NE + expert];
            float* cp = C + (size_t)cr * N;
            #pragma unroll
            for (int j = 0; j < 8; j++) {
                int c = ntile + ((j < 4) ? (tx * 4 + j) : (64 + tx * 4 + j - 4));
                cp[c] += wgt * (acc[i][j] + bias[c]);
            }
        } else if (mode == 1) {
            float* cp = C + (size_t)r * N;
            const float* rp = R + (size_t)r * N;
            #pragma unroll
            for (int j = 0; j < 8; j++) {
                int c = ntile + ((j < 4) ? (tx * 4 + j) : (64 + tx * 4 + j - 4));
                cp[c] = acc[i][j] + bias[c] + rp[c];
            }
        } else if (mode == 3) {
            float* cp = C + (size_t)r * N;
            const float* rp = R + (size_t)r * N;
            #pragma unroll
            for (int j = 0; j < 8; j++) {
                int c = ntile + ((j < 4) ? (tx * 4 + j) : (64 + tx * 4 + j - 4));
                cp[c] = silu_f(rp[c]) * (acc[i][j] + bias[c]);
            }
        } else {
            float* cp = C + (size_t)r * N;
            #pragma unroll
            for (int j = 0; j < 8; j++) {
                int c = ntile + ((j < 4) ? (tx * 4 + j) : (64 + tx * 4 + j - 4));
                cp[c] = acc[i][j] + bias[c];
            }
        }
    }
}

// ---------------- linear attention pass A: kv[64][64], ksum[64] per (b,h) ----------------
__global__ void attn_kv_kernel(const float* __restrict__ kbuf, const float* __restrict__ vbuf,
                               const float* __restrict__ mask) {
    int bh = blockIdx.x;
    int b = bh / NH, h = bh % NH;
    int tid = threadIdx.x;                          // 256
    __shared__ float Ks[32][64];
    __shared__ float Vs[32][64];
    __shared__ float ksum_s[64];
    if (tid < 64) ksum_s[tid] = 0.f;
    float acc[16];
    #pragma unroll
    for (int i = 0; i < 16; i++) acc[i] = 0.f;
    int e  = tid & 63;
    int d0 = tid >> 6;                              // 0..3
    int lr = tid >> 3;                              // 0..31 (load row)
    int lc = (tid & 7) * 8;                         // 0..56 (load col)
    const float* kb = kbuf + (size_t)b * SEQ * DIM + h * HD;
    const float* vb = vbuf + (size_t)b * SEQ * DIM + h * HD;
    for (int s0 = 0; s0 < SEQ; s0 += 32) {
        __syncthreads();
        float mval = mask[b * SEQ + s0 + lr];
        const float* kp = kb + (size_t)(s0 + lr) * DIM + lc;
        const float* vp = vb + (size_t)(s0 + lr) * DIM + lc;
        float4 k0 = *(const float4*)kp;       float4 k1 = *(const float4*)(kp + 4);
        float4 v0 = *(const float4*)vp;       float4 v1 = *(const float4*)(vp + 4);
        Ks[lr][lc + 0] = phi_f(k0.x) * mval;  Ks[lr][lc + 1] = phi_f(k0.y) * mval;
        Ks[lr][lc + 2] = phi_f(k0.z) * mval;  Ks[lr][lc + 3] = phi_f(k0.w) * mval;
        Ks[lr][lc + 4] = phi_f(k1.x) * mval;  Ks[lr][lc + 5] = phi_f(k1.y) * mval;
        Ks[lr][lc + 6] = phi_f(k1.z) * mval;  Ks[lr][lc + 7] = phi_f(k1.w) * mval;
        Vs[lr][lc + 0] = v0.x; Vs[lr][lc + 1] = v0.y; Vs[lr][lc + 2] = v0.z; Vs[lr][lc + 3] = v0.w;
        Vs[lr][lc + 4] = v1.x; Vs[lr][lc + 5] = v1.y; Vs[lr][lc + 6] = v1.z; Vs[lr][lc + 7] = v1.w;
        __syncthreads();
        if (tid < 64) {
            float t = 0.f;
            #pragma unroll
            for (int r2 = 0; r2 < 32; r2++) t += Ks[r2][tid];
            ksum_s[tid] += t;
        }
        for (int r2 = 0; r2 < 32; r2++) {
            float ve = Vs[r2][e];
            #pragma unroll
            for (int i = 0; i < 16; i++) acc[i] += Ks[r2][d0 + 4 * i] * ve;
        }
    }
    float* kvp = g_kv + (size_t)bh * HD * HD;
    #pragma unroll
    for (int i = 0; i < 16; i++) kvp[(d0 + 4 * i) * HD + e] = acc[i];
    if (tid < 64) g_ksum[bh * HD + tid] = ksum_s[tid];
}

// ---------------- linear attention pass B: attn[s,e] = (phiq·kv) / (phiq·ksum + eps) ----------------
__global__ void attn_out_kernel(const float* __restrict__ qbuf, float* __restrict__ attn) {
    int blk = blockIdx.x;                           // 48 * 16
    int bh = blk >> 4;
    int sc = blk & 15;
    int b = bh / NH, h = bh % NH;
    int tid = threadIdx.x;                          // 128
    __shared__ float kvs[HD * HD];
    __shared__ float ks_s[HD];
    const float* kvp = g_kv + (size_t)bh * HD * HD;
    #pragma unroll
    for (int i = 0; i < 32; i++) kvs[tid + i * 128] = kvp[tid + i * 128];
    if (tid < 64) ks_s[tid] = g_ksum[bh * HD + tid];
    __syncthreads();
    int s = sc * 128 + tid;
    size_t row = (size_t)b * SEQ + s;
    const float* qp = qbuf + row * DIM + h * HD;
    float pq[64];
    #pragma unroll
    for (int d = 0; d < 64; d++) pq[d] = phi_f(qp[d]);
    float z = 0.f;
    #pragma unroll
    for (int d = 0; d < 64; d++) z += pq[d] * ks_s[d];
    float invz = 1.f / (z + 1e-6f);
    float* op = attn + row * DIM + h * HD;
    for (int e = 0; e < 64; e++) {
        float num = 0.f;
        #pragma unroll
        for (int d = 0; d < 64; d++) num += pq[d] * kvs[d * 64 + e];
        op[e] = num * invz;
    }
}

// ---------------- gating: softmax -> top2 -> normalize -> combine + expert lists ----------------
__global__ void zero_cnt_kernel() { if (threadIdx.x < NE) g_cnt[threadIdx.x] = 0; }

__global__ void gate_kernel(const float* __restrict__ x2, const float* __restrict__ gw,
                            const float* __restrict__ gb) {
    int t = blockIdx.x * 8 + (threadIdx.x >> 5);    // one warp per token
    int lane = threadIdx.x & 31;
    const float* xr = x2 + (size_t)t * DIM;
    float l0 = 0.f, l1 = 0.f, l2 = 0.f, l3 = 0.f;
    for (int d = lane; d < DIM; d += 32) {
        float xv = xr[d];
        const float* gr = gw + d * NE;
        l0 += xv * gr[0]; l1 += xv * gr[1]; l2 += xv * gr[2]; l3 += xv * gr[3];
    }
    #pragma unroll
    for (int o = 16; o; o >>= 1) {
        l0 += __shfl_down_sync(0xffffffffu, l0, o);
        l1 += __shfl_down_sync(0xffffffffu, l1, o);
        l2 += __shfl_down_sync(0xffffffffu, l2, o);
        l3 += __shfl_down_sync(0xffffffffu, l3, o);
    }
    if (lane == 0) {
        float l[4] = {l0 + gb[0], l1 + gb[1], l2 + gb[2], l3 + gb[3]};
        float mx = fmaxf(fmaxf(l[0], l[1]), fmaxf(l[2], l[3]));
        float p[4]; float s = 0.f;
        #pragma unroll
        for (int e = 0; e < 4; e++) { p[e] = expf(l[e] - mx); s += p[e]; }
        #pragma unroll
        for (int e = 0; e < 4; e++) p[e] /= s;
        int i1 = 0;
        #pragma unroll
        for (int e = 1; e < 4; e++) if (p[e] > p[i1]) i1 = e;
        int i2 = -1;
        #pragma unroll
        for (int e = 0; e < 4; e++) if (e != i1 && (i2 < 0 || p[e] > p[i2])) i2 = e;
        float ws = p[i1] + p[i2] + 1e-6f;
        float w1 = p[i1] / ws, w2 = p[i2] / ws;
        float* cb = g_comb + t * NE;
        cb[0] = 0.f; cb[1] = 0.f; cb[2] = 0.f; cb[3] = 0.f;
        cb[i1] = w1; cb[i2] = w2;
        int pos1 = atomicAdd(&g_cnt[i1], 1); g_idx[i1 * NTOK + pos1] = t;
        int pos2 = atomicAdd(&g_cnt[i2], 1); g_idx[i2 * NTOK + pos2] = t;
    }
}

// ---------------- host orchestration ----------------
extern "C" void kernel_launch(void* const* d_in, const int* in_sizes, int n_in,
                              void* d_out, int out_size) {
    const float* x    = (const float*)d_in[0];
    const float* mask = (const float*)d_in[1];
    const float* qw1 = (const float*)d_in[2];  const float* qb1 = (const float*)d_in[3];
    const float* qw2 = (const float*)d_in[4];  const float* qb2 = (const float*)d_in[5];
    const float* kw1 = (const float*)d_in[6];  const float* kb1 = (const float*)d_in[7];
    const float* kw2 = (const float*)d_in[8];  const float* kb2 = (const float*)d_in[9];
    const float* vw1 = (const float*)d_in[10]; const float* vb1 = (const float*)d_in[11];
    const float* vw2 = (const float*)d_in[12]; const float* vb2 = (const float*)d_in[13];
    const float* wo  = (const float*)d_in[14]; const float* bo  = (const float*)d_in[15];
    const float* ew1 = (const float*)d_in[16]; const float* eb1 = (const float*)d_in[17];
    const float* ew3 = (const float*)d_in[18]; const float* eb3 = (const float*)d_in[19];
    const float* ew2 = (const float*)d_in[20]; const float* eb2 = (const float*)d_in[21];
    const float* gw  = (const float*)d_in[22]; const float* gb  = (const float*)d_in[23];
    const float* g1  = (const float*)d_in[24]; const float* be1 = (const float*)d_in[25];
    const float* g2  = (const float*)d_in[26]; const float* be2 = (const float*)d_in[27];
    float* out = (float*)d_out;

    float *p_x2, *p_t1, *p_q, *p_k, *p_v, *p_comb;
    int *p_cnt, *p_idx;
    cudaGetSymbolAddress((void**)&p_x2,   g_x2);
    cudaGetSymbolAddress((void**)&p_t1,   g_t1);
    cudaGetSymbolAddress((void**)&p_q,    g_q);
    cudaGetSymbolAddress((void**)&p_k,    g_k);
    cudaGetSymbolAddress((void**)&p_v,    g_v);
    cudaGetSymbolAddress((void**)&p_comb, g_comb);
    cudaGetSymbolAddress((void**)&p_cnt,  g_cnt);
    cudaGetSymbolAddress((void**)&p_idx,  g_idx);

    zero_cnt_kernel<<<1, 32>>>();

    // ---- pre-LN + QKV GLU projections (GLU fused into 2nd GEMM epilogue) ----
    ln_kernel<<<NTOK, 256>>>(x, g1, be1, p_x2);
    const float* W1s[3] = {qw1, kw1, vw1}; const float* B1s[3] = {qb1, kb1, vb1};
    const float* W2s[3] = {qw2, kw2, vw2}; const float* B2s[3] = {qb2, kb2, vb2};
    float* OUTs[3] = {p_q, p_k, p_v};
    for (int i = 0; i < 3; i++) {
        sgemm_kernel<<<dim3(DIM / 128, NTOK / 128), 256>>>(
            p_x2, W1s[i], B1s[i], p_t1, NTOK, DIM, DIM, nullptr, nullptr, 0, nullptr, nullptr, 0);
        sgemm_kernel<<<dim3(DIM / 128, NTOK / 128), 256>>>(
            p_x2, W2s[i], B2s[i], OUTs[i], NTOK, DIM, DIM, nullptr, nullptr, 3, p_t1, nullptr, 0);
    }

    // ---- linear attention ----
    attn_kv_kernel<<<BATCH * NH, 256>>>(p_k, p_v, mask);
    attn_out_kernel<<<BATCH * NH * (SEQ / 128), 128>>>(p_q, p_t1);   // attn -> g_t1

    // ---- out projection + residual: out = attn @ wo + bo + x ----
    sgemm_kernel<<<dim3(DIM / 128, NTOK / 128), 256>>>(
        p_t1, wo, bo, out, NTOK, DIM, DIM, nullptr, nullptr, 1, x, nullptr, 0);

    // ---- LN2 + gating ----
    ln_kernel<<<NTOK, 256>>>(out, g2, be2, p_x2);
    gate_kernel<<<NTOK / 8, 256>>>(p_x2, gw, gb);

    // ---- sparse MoE: per expert, GEMM over its token list, scatter-accumulate into out ----
    for (int e = 0; e < NE; e++) {
        const int* cnt  = p_cnt + e;
        const int* idxe = p_idx + e * NTOK;
        // t1 = x2[idx] @ ew1 + eb1   (compacted rows)
        sgemm_kernel<<<dim3(FF / 128, NTOK / 128), 256>>>(
            p_x2, ew1 + (size_t)e * DIM * FF, eb1 + e * FF, p_t1,
            NTOK, FF, DIM, idxe, cnt, 0, nullptr, nullptr, 0);
        // t1 = silu(t1) * (x2[idx] @ ew3 + eb3)   (fused GLU epilogue, in-place)
        sgemm_kernel<<<dim3(FF / 128, NTOK / 128), 256>>>(
            p_x2, ew3 + (size_t)e * DIM * FF, eb3 + e * FF, p_t1,
            NTOK, FF, DIM, idxe, cnt, 3, p_t1, nullptr, 0);
        // out[idx] += comb * (t1 @ ew2 + eb2)
        sgemm_kernel<<<dim3(DIM / 128, NTOK / 128), 256>>>(
            p_t1, ew2 + (size_t)e * FF * DIM, eb2 + e * DIM, out,
            NTOK, DIM, FF, idxe, cnt, 2, nullptr, p_comb, e);
    }
}

// round 6
// speedup vs baseline: 1.6824x; 1.6824x over previous
#include <cuda_runtime.h>
#include <cuda_bf16.h>
#include <math.h>
#include <stdint.h>

#define NTOK  8192
#define DIM   768
#define NH    12
#define HD    64
#define FF    3072
#define NE    4
#define SEQ   2048
#define BATCH 4

// ---------------- scratch (static device globals; no allocation) ----------------
__device__ float g_x2[NTOK * DIM];
__device__ float g_t1[NTOK * FF];
__device__ float g_q[NTOK * DIM];
__device__ float g_k[NTOK * DIM];
__device__ float g_v[NTOK * DIM];
__device__ float g_kv[BATCH * NH * HD * HD];
__device__ float g_ksum[BATCH * NH * HD];
__device__ float g_comb[NTOK * NE];
__device__ int   g_cnt[NE];
__device__ int   g_idx[NE * NTOK];

// transposed + bf16-split weights: Wt[N][K] row-major
#define W768   (768 * 768)
#define W_DF   (768 * 3072)
#define WT_TOT (7 * W768 + 12 * W_DF)
__device__ __nv_bfloat16 g_wt_hi[WT_TOT];
__device__ __nv_bfloat16 g_wt_lo[WT_TOT];

__device__ __forceinline__ float phi_f(float x)  { return x > 0.f ? x + 1.f : expf(x); }
__device__ __forceinline__ float silu_f(float x) { return x / (1.f + expf(-x)); }

__device__ __forceinline__ uint32_t smem_u32(const void* p) {
    uint32_t a;
    asm("{ .reg .u64 t; cvta.to.shared.u64 t, %1; cvt.u32.u64 %0, t; }" : "=r"(a) : "l"(p));
    return a;
}
__device__ __forceinline__ void ldsm_x4(uint32_t& r0, uint32_t& r1, uint32_t& r2, uint32_t& r3, uint32_t addr) {
    asm volatile("ldmatrix.sync.aligned.m8n8.x4.shared.b16 {%0,%1,%2,%3}, [%4];"
                 : "=r"(r0), "=r"(r1), "=r"(r2), "=r"(r3) : "r"(addr));
}
__device__ __forceinline__ void mma_bf16(float* c, const uint32_t* a, const uint32_t* b) {
    asm volatile("mma.sync.aligned.m16n8k16.row.col.f32.bf16.bf16.f32 "
                 "{%0,%1,%2,%3}, {%4,%5,%6,%7}, {%8,%9}, {%0,%1,%2,%3};"
                 : "+f"(c[0]), "+f"(c[1]), "+f"(c[2]), "+f"(c[3])
                 : "r"(a[0]), "r"(a[1]), "r"(a[2]), "r"(a[3]), "r"(b[0]), "r"(b[1]));
}
__device__ __forceinline__ void cp16(uint32_t smem_addr, const void* g) {
    asm volatile("cp.async.ca.shared.global [%0], [%1], 16;" :: "r"(smem_addr), "l"(g));
}
__device__ __forceinline__ void cp_commit() { asm volatile("cp.async.commit_group;"); }
__device__ __forceinline__ void cp_wait0()  { asm volatile("cp.async.wait_group 0;"); }

// ====================== bf16 tensor-core GEMM: C[M,N] = A[M,K] @ W[K,N] ======================
// Bh/Bl = transposed split weights [N][K] bf16. CTA tile 128x128, BK=32.
// 8 warps = 2(m) x 4(n), warp tile 64x32. hi/lo 3-pass accumulate in fp32.
// mode 0: C = acc + bias                 (idx remaps A rows; cntPtr overrides M)
// mode 1: C = acc + bias + R
// mode 2: C[idx[r]] += comb[idx[r]*NE+expert] * (acc + bias)
// mode 3: C = silu(R) * (acc + bias)
#define LDA    40
#define STG_E  (128 * LDA)                 // elems per array per stage
#define GEMM_SMEM (2 * 4 * STG_E * 2)      // 81920 bytes

__global__ __launch_bounds__(256) void gemm_bf16(
    const float* __restrict__ A,
    const __nv_bfloat16* __restrict__ Bh, const __nv_bfloat16* __restrict__ Bl,
    const float* __restrict__ bias, float* __restrict__ C,
    int M, int N, int K,
    const int* __restrict__ idx, const int* __restrict__ cntPtr,
    int mode, const float* __restrict__ R,
    const float* __restrict__ comb, int expert)
{
    extern __shared__ __nv_bfloat16 sm[];
    int Mcur = cntPtr ? *cntPtr : M;
    int mtile = blockIdx.y * 128;
    if (mtile >= Mcur) return;
    int ntile = blockIdx.x * 128;
    int tid  = threadIdx.x;
    int wid  = tid >> 5;
    int lane = tid & 31;
    int wm = wid >> 2, wn = wid & 3;

    uint32_t sbase = smem_u32(sm);

    // loader mapping: row = tid>>1 (0..127), kof = (tid&1)*16
    int lrow = tid >> 1;
    int kof  = (tid & 1) * 16;
    int grow = mtile + lrow;
    bool valid = grow < Mcur;
    const float* ap = nullptr;
    if (valid) {
        int arow = (mode != 2 && idx) ? idx[grow] : grow;
        ap = A + (size_t)arow * K + kof;
    }
    const __nv_bfloat16* bph = Bh + (size_t)(ntile + lrow) * K + kof;
    const __nv_bfloat16* bpl = Bl + (size_t)(ntile + lrow) * K + kof;
    uint32_t sts_off = (uint32_t)(lrow * LDA + kof) * 2;   // byte off within one array

    // issue B cp.async for stage kt into buffer s
    auto loadB = [&](int kt, int s) {
        uint32_t base = sbase + (uint32_t)(s * 4 * STG_E) * 2;
        uint32_t dh = base + (uint32_t)(2 * STG_E) * 2 + sts_off;
        uint32_t dl = base + (uint32_t)(3 * STG_E) * 2 + sts_off;
        const __nv_bfloat16* ph = bph + kt * 32;
        const __nv_bfloat16* pl = bpl + kt * 32;
        cp16(dh,      ph);     cp16(dh + 16, ph + 8);
        cp16(dl,      pl);     cp16(dl + 16, pl + 8);
        cp_commit();
    };

    float acc[4][4][4];
    #pragma unroll
    for (int i = 0; i < 4; i++)
        #pragma unroll
        for (int j = 0; j < 4; j++)
            #pragma unroll
            for (int q = 0; q < 4; q++) acc[i][j][q] = 0.f;

    int lrow16 = lane & 15;
    int lcol8  = (lane >> 4) << 3;

    float4 pa[4];
    auto ldA = [&](int kt) {
        if (valid) {
            const float* p = ap + kt * 32;
            pa[0] = *(const float4*)(p + 0);
            pa[1] = *(const float4*)(p + 4);
            pa[2] = *(const float4*)(p + 8);
            pa[3] = *(const float4*)(p + 12);
        } else {
            pa[0] = pa[1] = pa[2] = pa[3] = make_float4(0.f, 0.f, 0.f, 0.f);
        }
    };
    // convert regs -> bf16 hi/lo and store into stage s
    auto stA = [&](int s) {
        uint32_t base = s * 4 * STG_E;
        __nv_bfloat16* Ah = sm + base;
        __nv_bfloat16* Al = sm + base + STG_E;
        uint32_t hu[8], lu[8];
        #pragma unroll
        for (int j = 0; j < 4; j++) {
            float v[4] = {pa[j].x, pa[j].y, pa[j].z, pa[j].w};
            #pragma unroll
            for (int q = 0; q < 2; q++) {
                float x0 = v[2 * q], x1 = v[2 * q + 1];
                __nv_bfloat162 hp = __floats2bfloat162_rn(x0, x1);
                hu[j * 2 + q] = *reinterpret_cast<uint32_t*>(&hp);
                float r0 = x0 - __low2float(hp), r1 = x1 - __high2float(hp);
                __nv_bfloat162 lp = __floats2bfloat162_rn(r0, r1);
                lu[j * 2 + q] = *reinterpret_cast<uint32_t*>(&lp);
            }
        }
        uint32_t* dh = (uint32_t*)(Ah + lrow * LDA + kof);
        uint32_t* dl = (uint32_t*)(Al + lrow * LDA + kof);
        *(uint4*)(dh)     = make_uint4(hu[0], hu[1], hu[2], hu[3]);
        *(uint4*)(dh + 4) = make_uint4(hu[4], hu[5], hu[6], hu[7]);
        *(uint4*)(dl)     = make_uint4(lu[0], lu[1], lu[2], lu[3]);
        *(uint4*)(dl + 4) = make_uint4(lu[4], lu[5], lu[6], lu[7]);
    };

    auto compute = [&](int s) {
        uint32_t base = sbase + (uint32_t)(s * 4 * STG_E) * 2;
        uint32_t bAh = base;
        uint32_t bAl = base + (uint32_t)STG_E * 2;
        uint32_t bBh = base + (uint32_t)(2 * STG_E) * 2;
        uint32_t bBl = base + (uint32_t)(3 * STG_E) * 2;
        #pragma unroll
        for (int ks = 0; ks < 2; ks++) {
            int kc = ks * 16 + lcol8;
            // B fragments: 4 n8 tiles (hi & lo)
            uint32_t bh[4][2], bl[4][2];
            #pragma unroll
            for (int half = 0; half < 2; half++) {
                uint32_t off = (uint32_t)((wn * 32 + half * 16 + lrow16) * LDA + kc) * 2;
                uint32_t r0, r1, r2, r3;
                ldsm_x4(r0, r1, r2, r3, bBh + off);
                bh[half * 2 + 0][0] = r0; bh[half * 2 + 0][1] = r2;
                bh[half * 2 + 1][0] = r1; bh[half * 2 + 1][1] = r3;
                ldsm_x4(r0, r1, r2, r3, bBl + off);
                bl[half * 2 + 0][0] = r0; bl[half * 2 + 0][1] = r2;
                bl[half * 2 + 1][0] = r1; bl[half * 2 + 1][1] = r3;
            }
            #pragma unroll
            for (int mt = 0; mt < 4; mt++) {
                uint32_t off = (uint32_t)((wm * 64 + mt * 16 + lrow16) * LDA + kc) * 2;
                uint32_t ah[4], al[4];
                ldsm_x4(ah[0], ah[1], ah[2], ah[3], bAh + off);
                ldsm_x4(al[0], al[1], al[2], al[3], bAl + off);
                #pragma unroll
                for (int nt = 0; nt < 4; nt++) {
                    mma_bf16(acc[mt][nt], ah, bh[nt]);
                    mma_bf16(acc[mt][nt], ah, bl[nt]);
                    mma_bf16(acc[mt][nt], al, bh[nt]);
                }
            }
        }
    };

    // prologue: stage 0
    loadB(0, 0);
    ldA(0);
    stA(0);
    cp_wait0();
    __syncthreads();

    int KT = K >> 5;
    for (int kt = 0; kt < KT; kt++) {
        int cur = kt & 1;
        bool more = (kt + 1 < KT);
        if (more) { loadB(kt + 1, cur ^ 1); ldA(kt + 1); }
        compute(cur);
        if (more) {
            stA(cur ^ 1);
            cp_wait0();
            __syncthreads();
        }
    }

    // -------- epilogue: direct fragment stores (float2) --------
    #pragma unroll
    for (int mt = 0; mt < 4; mt++) {
        int r0 = mtile + wm * 64 + mt * 16 + (lane >> 2);
        int r1 = r0 + 8;
        #pragma unroll
        for (int nt = 0; nt < 4; nt++) {
            int c = ntile + wn * 32 + nt * 8 + 2 * (lane & 3);
            float b0 = bias[c], b1 = bias[c + 1];
            float v00 = acc[mt][nt][0] + b0, v01 = acc[mt][nt][1] + b1;
            float v10 = acc[mt][nt][2] + b0, v11 = acc[mt][nt][3] + b1;
            if (mode == 2) {
                if (r0 < Mcur) {
                    int cr = idx[r0]; float w = comb[cr * NE + expert];
                    float* cp = C + (size_t)cr * N + c;
                    cp[0] += w * v00; cp[1] += w * v01;
                }
                if (r1 < Mcur) {
                    int cr = idx[r1]; float w = comb[cr * NE + expert];
                    float* cp = C + (size_t)cr * N + c;
                    cp[0] += w * v10; cp[1] += w * v11;
                }
            } else if (mode == 1) {
                if (r0 < Mcur) {
                    const float* rp = R + (size_t)r0 * N + c;
                    float* cp = C + (size_t)r0 * N + c;
                    cp[0] = v00 + rp[0]; cp[1] = v01 + rp[1];
                }
                if (r1 < Mcur) {
                    const float* rp = R + (size_t)r1 * N + c;
                    float* cp = C + (size_t)r1 * N + c;
                    cp[0] = v10 + rp[0]; cp[1] = v11 + rp[1];
                }
            } else if (mode == 3) {
                if (r0 < Mcur) {
                    const float* rp = R + (size_t)r0 * N + c;
                    float* cp = C + (size_t)r0 * N + c;
                    cp[0] = silu_f(rp[0]) * v00; cp[1] = silu_f(rp[1]) * v01;
                }
                if (r1 < Mcur) {
                    const float* rp = R + (size_t)r1 * N + c;
                    float* cp = C + (size_t)r1 * N + c;
                    cp[0] = silu_f(rp[0]) * v10; cp[1] = silu_f(rp[1]) * v11;
                }
            } else {
                if (r0 < Mcur) {
                    float* cp = C + (size_t)r0 * N + c;
                    cp[0] = v00; cp[1] = v01;
                }
                if (r1 < Mcur) {
                    float* cp = C + (size_t)r1 * N + c;
                    cp[0] = v10; cp[1] = v11;
                }
            }
        }
    }
}

// ============== weight transpose + bf16 split: W[K,N] -> Wt_hi/lo[N,K] ==============
__global__ void tsplit_kernel(const float* __restrict__ W, __nv_bfloat16* __restrict__ Th,
                              __nv_bfloat16* __restrict__ Tl, int K, int N) {
    __shared__ float t[32][33];
    int tx = threadIdx.x & 31, ty = threadIdx.x >> 5;
    int n0 = blockIdx.x * 32, k0 = blockIdx.y * 32;
    #pragma unroll
    for (int i = 0; i < 4; i++)
        t[ty + i * 8][tx] = W[(size_t)(k0 + ty + i * 8) * N + n0 + tx];
    __syncthreads();
    #pragma unroll
    for (int i = 0; i < 4; i++) {
        int n = n0 + ty + i * 8, k = k0 + tx;
        float v = t[tx][ty + i * 8];
        __nv_bfloat16 h = __float2bfloat16(v);
        float r = v - __bfloat162float(h);
        Th[(size_t)n * K + k] = h;
        Tl[(size_t)n * K + k] = __float2bfloat16(r);
    }
}

// ---------------- LayerNorm ----------------
__global__ void ln_kernel(const float* __restrict__ X, const float* __restrict__ g,
                          const float* __restrict__ be, float* __restrict__ out) {
    int row = blockIdx.x;
    int tid = threadIdx.x;
    __shared__ float red[256];
    __shared__ float s_m, s_r;
    const float* xr = X + (size_t)row * DIM;
    float v0 = xr[tid], v1 = xr[tid + 256], v2 = xr[tid + 512];
    red[tid] = v0 + v1 + v2;
    __syncthreads();
    for (int o = 128; o > 0; o >>= 1) { if (tid < o) red[tid] += red[tid + o]; __syncthreads(); }
    if (tid == 0) s_m = red[0] * (1.f / DIM);
    __syncthreads();
    float m = s_m;
    float d0 = v0 - m, d1 = v1 - m, d2 = v2 - m;
    red[tid] = d0 * d0 + d1 * d1 + d2 * d2;
    __syncthreads();
    for (int o = 128; o > 0; o >>= 1) { if (tid < o) red[tid] += red[tid + o]; __syncthreads(); }
    if (tid == 0) s_r = rsqrtf(red[0] * (1.f / DIM) + 1e-5f);
    __syncthreads();
    float r = s_r;
    float* orow = out + (size_t)row * DIM;
    orow[tid]       = d0 * r * g[tid]       + be[tid];
    orow[tid + 256] = d1 * r * g[tid + 256] + be[tid + 256];
    orow[tid + 512] = d2 * r * g[tid + 512] + be[tid + 512];
}

// ---------------- linear attention pass A: kv[64][64], ksum[64] per (b,h) ----------------
__global__ void attn_kv_kernel(const float* __restrict__ kbuf, const float* __restrict__ vbuf,
                               const float* __restrict__ mask) {
    int bh = blockIdx.x;
    int b = bh / NH, h = bh % NH;
    int tid = threadIdx.x;                          // 256
    __shared__ float Ks[32][64];
    __shared__ float Vs[32][64];
    __shared__ float ksum_s[64];
    if (tid < 64) ksum_s[tid] = 0.f;
    float acc[16];
    #pragma unroll
    for (int i = 0; i < 16; i++) acc[i] = 0.f;
    int e  = tid & 63;
    int d0 = tid >> 6;
    int lr = tid >> 3;
    int lc = (tid & 7) * 8;
    const float* kb = kbuf + (size_t)b * SEQ * DIM + h * HD;
    const float* vb = vbuf + (size_t)b * SEQ * DIM + h * HD;
    for (int s0 = 0; s0 < SEQ; s0 += 32) {
        __syncthreads();
        float mval = mask[b * SEQ + s0 + lr];
        const float* kp = kb + (size_t)(s0 + lr) * DIM + lc;
        const float* vp = vb + (size_t)(s0 + lr) * DIM + lc;
        float4 k0 = *(const float4*)kp;       float4 k1 = *(const float4*)(kp + 4);
        float4 v0 = *(const float4*)vp;       float4 v1 = *(const float4*)(vp + 4);
        Ks[lr][lc + 0] = phi_f(k0.x) * mval;  Ks[lr][lc + 1] = phi_f(k0.y) * mval;
        Ks[lr][lc + 2] = phi_f(k0.z) * mval;  Ks[lr][lc + 3] = phi_f(k0.w) * mval;
        Ks[lr][lc + 4] = phi_f(k1.x) * mval;  Ks[lr][lc + 5] = phi_f(k1.y) * mval;
        Ks[lr][lc + 6] = phi_f(k1.z) * mval;  Ks[lr][lc + 7] = phi_f(k1.w) * mval;
        Vs[lr][lc + 0] = v0.x; Vs[lr][lc + 1] = v0.y; Vs[lr][lc + 2] = v0.z; Vs[lr][lc + 3] = v0.w;
        Vs[lr][lc + 4] = v1.x; Vs[lr][lc + 5] = v1.y; Vs[lr][lc + 6] = v1.z; Vs[lr][lc + 7] = v1.w;
        __syncthreads();
        if (tid < 64) {
            float t = 0.f;
            #pragma unroll
            for (int r2 = 0; r2 < 32; r2++) t += Ks[r2][tid];
            ksum_s[tid] += t;
        }
        for (int r2 = 0; r2 < 32; r2++) {
            float ve = Vs[r2][e];
            #pragma unroll
            for (int i = 0; i < 16; i++) acc[i] += Ks[r2][d0 + 4 * i] * ve;
        }
    }
    float* kvp = g_kv + (size_t)bh * HD * HD;
    #pragma unroll
    for (int i = 0; i < 16; i++) kvp[(d0 + 4 * i) * HD + e] = acc[i];
    if (tid < 64) g_ksum[bh * HD + tid] = ksum_s[tid];
}

// ---------------- linear attention pass B ----------------
__global__ void attn_out_kernel(const float* __restrict__ qbuf, float* __restrict__ attn) {
    int blk = blockIdx.x;
    int bh = blk >> 4;
    int sc = blk & 15;
    int b = bh / NH, h = bh % NH;
    int tid = threadIdx.x;                          // 128
    __shared__ float kvs[HD * HD];
    __shared__ float ks_s[HD];
    const float* kvp = g_kv + (size_t)bh * HD * HD;
    #pragma unroll
    for (int i = 0; i < 32; i++) kvs[tid + i * 128] = kvp[tid + i * 128];
    if (tid < 64) ks_s[tid] = g_ksum[bh * HD + tid];
    __syncthreads();
    int s = sc * 128 + tid;
    size_t row = (size_t)b * SEQ + s;
    const float* qp = qbuf + row * DIM + h * HD;
    float pq[64];
    #pragma unroll
    for (int d = 0; d < 64; d++) pq[d] = phi_f(qp[d]);
    float z = 0.f;
    #pragma unroll
    for (int d = 0; d < 64; d++) z += pq[d] * ks_s[d];
    float invz = 1.f / (z + 1e-6f);
    float* op = attn + row * DIM + h * HD;
    for (int e = 0; e < 64; e++) {
        float num = 0.f;
        #pragma unroll
        for (int d = 0; d < 64; d++) num += pq[d] * kvs[d * 64 + e];
        op[e] = num * invz;
    }
}

// ---------------- gating ----------------
__global__ void zero_cnt_kernel() { if (threadIdx.x < NE) g_cnt[threadIdx.x] = 0; }

__global__ void gate_kernel(const float* __restrict__ x2, const float* __restrict__ gw,
                            const float* __restrict__ gb) {
    int t = blockIdx.x * 8 + (threadIdx.x >> 5);
    int lane = threadIdx.x & 31;
    const float* xr = x2 + (size_t)t * DIM;
    float l0 = 0.f, l1 = 0.f, l2 = 0.f, l3 = 0.f;
    for (int d = lane; d < DIM; d += 32) {
        float xv = xr[d];
        const float* gr = gw + d * NE;
        l0 += xv * gr[0]; l1 += xv * gr[1]; l2 += xv * gr[2]; l3 += xv * gr[3];
    }
    #pragma unroll
    for (int o = 16; o; o >>= 1) {
        l0 += __shfl_down_sync(0xffffffffu, l0, o);
        l1 += __shfl_down_sync(0xffffffffu, l1, o);
        l2 += __shfl_down_sync(0xffffffffu, l2, o);
        l3 += __shfl_down_sync(0xffffffffu, l3, o);
    }
    if (lane == 0) {
        float l[4] = {l0 + gb[0], l1 + gb[1], l2 + gb[2], l3 + gb[3]};
        float mx = fmaxf(fmaxf(l[0], l[1]), fmaxf(l[2], l[3]));
        float p[4]; float s = 0.f;
        #pragma unroll
        for (int e = 0; e < 4; e++) { p[e] = expf(l[e] - mx); s += p[e]; }
        #pragma unroll
        for (int e = 0; e < 4; e++) p[e] /= s;
        int i1 = 0;
        #pragma unroll
        for (int e = 1; e < 4; e++) if (p[e] > p[i1]) i1 = e;
        int i2 = -1;
        #pragma unroll
        for (int e = 0; e < 4; e++) if (e != i1 && (i2 < 0 || p[e] > p[i2])) i2 = e;
        float ws = p[i1] + p[i2] + 1e-6f;
        float w1 = p[i1] / ws, w2 = p[i2] / ws;
        float* cb = g_comb + t * NE;
        cb[0] = 0.f; cb[1] = 0.f; cb[2] = 0.f; cb[3] = 0.f;
        cb[i1] = w1; cb[i2] = w2;
        int pos1 = atomicAdd(&g_cnt[i1], 1); g_idx[i1 * NTOK + pos1] = t;
        int pos2 = atomicAdd(&g_cnt[i2], 1); g_idx[i2 * NTOK + pos2] = t;
    }
}

// ---------------- host orchestration ----------------
extern "C" void kernel_launch(void* const* d_in, const int* in_sizes, int n_in,
                              void* d_out, int out_size) {
    const float* x    = (const float*)d_in[0];
    const float* mask = (const float*)d_in[1];
    const float* qw1 = (const float*)d_in[2];  const float* qb1 = (const float*)d_in[3];
    const float* qw2 = (const float*)d_in[4];  const float* qb2 = (const float*)d_in[5];
    const float* kw1 = (const float*)d_in[6];  const float* kb1 = (const float*)d_in[7];
    const float* kw2 = (const float*)d_in[8];  const float* kb2 = (const float*)d_in[9];
    const float* vw1 = (const float*)d_in[10]; const float* vb1 = (const float*)d_in[11];
    const float* vw2 = (const float*)d_in[12]; const float* vb2 = (const float*)d_in[13];
    const float* wo  = (const float*)d_in[14]; const float* bo  = (const float*)d_in[15];
    const float* ew1 = (const float*)d_in[16]; const float* eb1 = (const float*)d_in[17];
    const float* ew3 = (const float*)d_in[18]; const float* eb3 = (const float*)d_in[19];
    const float* ew2 = (const float*)d_in[20]; const float* eb2 = (const float*)d_in[21];
    const float* gw  = (const float*)d_in[22]; const float* gb  = (const float*)d_in[23];
    const float* g1  = (const float*)d_in[24]; const float* be1 = (const float*)d_in[25];
    const float* g2  = (const float*)d_in[26]; const float* be2 = (const float*)d_in[27];
    float* out = (float*)d_out;

    float *p_x2, *p_t1, *p_q, *p_k, *p_v, *p_comb;
    int *p_cnt, *p_idx;
    __nv_bfloat16 *p_wh, *p_wl;
    cudaGetSymbolAddress((void**)&p_x2,   g_x2);
    cudaGetSymbolAddress((void**)&p_t1,   g_t1);
    cudaGetSymbolAddress((void**)&p_q,    g_q);
    cudaGetSymbolAddress((void**)&p_k,    g_k);
    cudaGetSymbolAddress((void**)&p_v,    g_v);
    cudaGetSymbolAddress((void**)&p_comb, g_comb);
    cudaGetSymbolAddress((void**)&p_cnt,  g_cnt);
    cudaGetSymbolAddress((void**)&p_idx,  g_idx);
    cudaGetSymbolAddress((void**)&p_wh,   g_wt_hi);
    cudaGetSymbolAddress((void**)&p_wl,   g_wt_lo);

    cudaFuncSetAttribute(gemm_bf16, cudaFuncAttributeMaxDynamicSharedMemorySize, GEMM_SMEM);

    size_t o_q1 = 0, o_q2 = 1ull * W768, o_k1 = 2ull * W768, o_k2 = 3ull * W768;
    size_t o_v1 = 4ull * W768, o_v2 = 5ull * W768, o_wo = 6ull * W768;
    size_t o_e1 = 7ull * W768;
    size_t o_e3 = 7ull * W768 + 4ull * W_DF;
    size_t o_e2 = 7ull * W768 + 8ull * W_DF;

    zero_cnt_kernel<<<1, 32>>>();

    // ---- transpose + split all weights ----
    {
        dim3 b(256);
        dim3 gdd(DIM / 32, DIM / 32);
        tsplit_kernel<<<gdd, b>>>(qw1, p_wh + o_q1, p_wl + o_q1, DIM, DIM);
        tsplit_kernel<<<gdd, b>>>(qw2, p_wh + o_q2, p_wl + o_q2, DIM, DIM);
        tsplit_kernel<<<gdd, b>>>(kw1, p_wh + o_k1, p_wl + o_k1, DIM, DIM);
        tsplit_kernel<<<gdd, b>>>(kw2, p_wh + o_k2, p_wl + o_k2, DIM, DIM);
        tsplit_kernel<<<gdd, b>>>(vw1, p_wh + o_v1, p_wl + o_v1, DIM, DIM);
        tsplit_kernel<<<gdd, b>>>(vw2, p_wh + o_v2, p_wl + o_v2, DIM, DIM);
        tsplit_kernel<<<gdd, b>>>(wo,  p_wh + o_wo, p_wl + o_wo, DIM, DIM);
        dim3 gdf(FF / 32, DIM / 32);   // W[768,3072]
        dim3 gfd(DIM / 32, FF / 32);   // W[3072,768]
        for (int e = 0; e < NE; e++) {
            tsplit_kernel<<<gdf, b>>>(ew1 + (size_t)e * DIM * FF, p_wh + o_e1 + (size_t)e * W_DF, p_wl + o_e1 + (size_t)e * W_DF, DIM, FF);
            tsplit_kernel<<<gdf, b>>>(ew3 + (size_t)e * DIM * FF, p_wh + o_e3 + (size_t)e * W_DF, p_wl + o_e3 + (size_t)e * W_DF, DIM, FF);
            tsplit_kernel<<<gfd, b>>>(ew2 + (size_t)e * FF * DIM, p_wh + o_e2 + (size_t)e * W_DF, p_wl + o_e2 + (size_t)e * W_DF, FF, DIM);
        }
    }

    // ---- LN1 + QKV GLU (fused epilogue) ----
    ln_kernel<<<NTOK, 256>>>(x, g1, be1, p_x2);
    {
        size_t o1[3] = {o_q1, o_k1, o_v1}, o2[3] = {o_q2, o_k2, o_v2};
        const float* B1s[3] = {qb1, kb1, vb1};
        const float* B2s[3] = {qb2, kb2, vb2};
        float* OUTs[3] = {p_q, p_k, p_v};
        for (int i = 0; i < 3; i++) {
            gemm_bf16<<<dim3(DIM / 128, NTOK / 128), 256, GEMM_SMEM>>>(
                p_x2, p_wh + o1[i], p_wl + o1[i], B1s[i], p_t1,
                NTOK, DIM, DIM, nullptr, nullptr, 0, nullptr, nullptr, 0);
            gemm_bf16<<<dim3(DIM / 128, NTOK / 128), 256, GEMM_SMEM>>>(
                p_x2, p_wh + o2[i], p_wl + o2[i], B2s[i], OUTs[i],
                NTOK, DIM, DIM, nullptr, nullptr, 3, p_t1, nullptr, 0);
        }
    }

    // ---- linear attention ----
    attn_kv_kernel<<<BATCH * NH, 256>>>(p_k, p_v, mask);
    attn_out_kernel<<<BATCH * NH * (SEQ / 128), 128>>>(p_q, p_t1);

    // ---- out projection + residual ----
    gemm_bf16<<<dim3(DIM / 128, NTOK / 128), 256, GEMM_SMEM>>>(
        p_t1, p_wh + o_wo, p_wl + o_wo, bo, out,
        NTOK, DIM, DIM, nullptr, nullptr, 1, x, nullptr, 0);

    // ---- LN2 + gating ----
    ln_kernel<<<NTOK, 256>>>(out, g2, be2, p_x2);
    gate_kernel<<<NTOK / 8, 256>>>(p_x2, gw, gb);

    // ---- sparse MoE ----
    for (int e = 0; e < NE; e++) {
        const int* cnt  = p_cnt + e;
        const int* idxe = p_idx + e * NTOK;
        size_t oe1 = o_e1 + (size_t)e * W_DF;
        size_t oe3 = o_e3 + (size_t)e * W_DF;
        size_t oe2 = o_e2 + (size_t)e * W_DF;
        gemm_bf16<<<dim3(FF / 128, NTOK / 128), 256, GEMM_SMEM>>>(
            p_x2, p_wh + oe1, p_wl + oe1, eb1 + e * FF, p_t1,
            NTOK, FF, DIM, idxe, cnt, 0, nullptr, nullptr, 0);
        gemm_bf16<<<dim3(FF / 128, NTOK / 128), 256, GEMM_SMEM>>>(
            p_x2, p_wh + oe3, p_wl + oe3, eb3 + e * FF, p_t1,
            NTOK, FF, DIM, idxe, cnt, 3, p_t1, nullptr, 0);
        gemm_bf16<<<dim3(DIM / 128, NTOK / 128), 256, GEMM_SMEM>>>(
            p_t1, p_wh + oe2, p_wl + oe2, eb2 + e * DIM, out,
            NTOK, DIM, FF, idxe, cnt, 2, nullptr, p_comb, e);
    }
}